// round 3
// baseline (speedup 1.0000x reference)
#include <cuda_runtime.h>

#define NN    50000
#define EE    800000
#define RR    4
#define NRSEG (NN*RR)        // 200000 (dst, relation) segments
#define DD    128
#define NG    128
#define NC    16

// ---------------- scratch (device globals: no allocation allowed) ----------
__device__ int   g_cnt[NRSEG];
__device__ int   g_off[NRSEG + 1];
__device__ int   g_cur[NRSEG];
__device__ int   g_srce[EE];
__device__ int   g_sege[EE];
__device__ int   g_srcs[EE];        // src node id, grouped by segment (CSR)
__device__ float g_s[NRSEG * DD];   // [N, R*D] aggregated means (102.4 MB)
__device__ float g_h1[NN * DD];
__device__ float g_h2[NN * DD];
__device__ int   g_gstart[NG + 1];

// ---------------- edge preprocessing ---------------------------------------
__global__ void zero_cnt_kernel() {
    int i = blockIdx.x * blockDim.x + threadIdx.x;
    if (i < NRSEG) g_cnt[i] = 0;
}

__global__ void hist_kernel(const int* __restrict__ ei,
                            const int* __restrict__ et) {
    int e = blockIdx.x * blockDim.x + threadIdx.x;
    if (e >= EE) return;
    int src = ei[e];
    int dst = ei[EE + e];
    int ty  = et[e];
    int seg = dst * RR + ty;
    g_srce[e] = src;
    g_sege[e] = seg;
    atomicAdd(&g_cnt[seg], 1);
}

// exclusive scan of g_cnt -> g_off (single block, 1024 threads, chunked)
__global__ void scan_kernel() {
    __shared__ int sh[1024];
    int t = threadIdx.x;
    const int C = (NRSEG + 1023) / 1024;   // 196
    int b = t * C;
    int e = min(b + C, NRSEG);
    int s = 0;
    for (int i = b; i < e; i++) s += g_cnt[i];
    sh[t] = s;
    __syncthreads();
    // Hillis-Steele inclusive scan over 1024 partials
    for (int d = 1; d < 1024; d <<= 1) {
        int v = (t >= d) ? sh[t - d] : 0;
        __syncthreads();
        sh[t] += v;
        __syncthreads();
    }
    int excl = sh[t] - s;               // exclusive prefix at chunk start
    if (t == 1023) g_off[NRSEG] = sh[1023];
    int a = excl;
    for (int i = b; i < e; i++) {
        g_off[i] = a;
        g_cur[i] = a;
        a += g_cnt[i];
    }
}

__global__ void scatter_kernel() {
    int e = blockIdx.x * blockDim.x + threadIdx.x;
    if (e >= EE) return;
    int seg = g_sege[e];
    int pos = atomicAdd(&g_cur[seg], 1);
    g_srcs[pos] = g_srce[e];
}

// ---------------- per-(dst,rel) segment mean: warp per segment -------------
// LAYER 0: reads input x (arg).  LAYER 1: reads g_h1 (symbol).
template<int LAYER>
__global__ void agg_kernel(const float4* __restrict__ Xin) {
    const float4* X4 = (LAYER == 0) ? Xin : (const float4*)g_h1;
    int w    = (blockIdx.x * blockDim.x + threadIdx.x) >> 5;
    int lane = threadIdx.x & 31;
    if (w >= NRSEG) return;
    int o0 = g_off[w];
    int o1 = g_off[w + 1];
    float4 acc = make_float4(0.f, 0.f, 0.f, 0.f);
    for (int i = o0; i < o1; i++) {
        int s = g_srcs[i];                     // broadcast load
        float4 v = X4[s * 32 + lane];          // gather one row chunk
        acc.x += v.x; acc.y += v.y; acc.z += v.z; acc.w += v.w;
    }
    float norm = (o1 > o0) ? 1.f / (float)(o1 - o0) : 0.f;
    acc.x *= norm; acc.y *= norm; acc.z *= norm; acc.w *= norm;
    ((float4*)g_s)[w * 32 + lane] = acc;
}

// ---------------- fused RGCN GEMM: out = relu([s | x] @ [Wrel;Wroot] + b) --
// M x 640 x 128, fp32. 128x128 block tile, 16 k-slice, 8x8 per thread.
// LAYER 0: Ax = x (arg),  out = g_h1.  LAYER 1: Ax = g_h1, out = g_h2.
#define TM 128
#define TN 128
#define TK 16

template<int LAYER>
__global__ void __launch_bounds__(256)
gemm_kernel(const float* __restrict__ Axin,  // [M,128] residual input (layer0)
            const float* __restrict__ Wrel,  // [512,128]
            const float* __restrict__ Wroot, // [128,128]
            const float* __restrict__ bias,  // [128]
            int M) {
    const float* Ax  = (LAYER == 0) ? Axin : g_h1;
    float*       out = (LAYER == 0) ? g_h1 : g_h2;

    __shared__ float Asm[TK][TM + 4];
    __shared__ float Bsm[TK][TN + 4];
    int tid = threadIdx.x;
    int m0  = blockIdx.x * TM;
    int tx  = tid & 15;
    int ty  = tid >> 4;

    float acc[8][8];
#pragma unroll
    for (int i = 0; i < 8; i++)
#pragma unroll
        for (int j = 0; j < 8; j++) acc[i][j] = 0.f;

    for (int ph = 0; ph < 2; ph++) {
        const float* A = ph ? Ax : g_s;
        const float* W = ph ? Wroot : Wrel;
        int SA = ph ? 128 : 512;
        int KT = ph ? (128 / TK) : (512 / TK);
        for (int kt = 0; kt < KT; kt++) {
            int k0 = kt * TK;
            // A tile -> Asm[k][m] (transposed), 512 float4 loads
#pragma unroll
            for (int i = 0; i < 2; i++) {
                int idx = tid + i * 256;
                int m   = idx >> 2;
                int kq  = idx & 3;
                int gm  = m0 + m;
                float4 v = make_float4(0.f, 0.f, 0.f, 0.f);
                if (gm < M)
                    v = *(const float4*)(A + (size_t)gm * SA + k0 + kq * 4);
                Asm[kq * 4 + 0][m] = v.x;
                Asm[kq * 4 + 1][m] = v.y;
                Asm[kq * 4 + 2][m] = v.z;
                Asm[kq * 4 + 3][m] = v.w;
            }
            // B tile (direct copy)
#pragma unroll
            for (int i = 0; i < 2; i++) {
                int idx = tid + i * 256;
                int k   = idx >> 5;
                int nq  = idx & 31;
                *(float4*)&Bsm[k][nq * 4] =
                    *(const float4*)(W + (k0 + k) * 128 + nq * 4);
            }
            __syncthreads();
#pragma unroll
            for (int k = 0; k < TK; k++) {
                float a[8], b[8];
                *(float4*)&a[0] = *(const float4*)&Asm[k][ty * 8];
                *(float4*)&a[4] = *(const float4*)&Asm[k][ty * 8 + 4];
                *(float4*)&b[0] = *(const float4*)&Bsm[k][tx * 8];
                *(float4*)&b[4] = *(const float4*)&Bsm[k][tx * 8 + 4];
#pragma unroll
                for (int i = 0; i < 8; i++)
#pragma unroll
                    for (int j = 0; j < 8; j++) acc[i][j] += a[i] * b[j];
            }
            __syncthreads();
        }
    }
    // epilogue: bias + relu
    float bv[8];
#pragma unroll
    for (int j = 0; j < 8; j++) bv[j] = bias[tx * 8 + j];
#pragma unroll
    for (int i = 0; i < 8; i++) {
        int gm = m0 + ty * 8 + i;
        if (gm >= M) continue;
#pragma unroll
        for (int j0 = 0; j0 < 8; j0 += 4) {
            float4 r;
            r.x = fmaxf(acc[i][j0 + 0] + bv[j0 + 0], 0.f);
            r.y = fmaxf(acc[i][j0 + 1] + bv[j0 + 1], 0.f);
            r.z = fmaxf(acc[i][j0 + 2] + bv[j0 + 2], 0.f);
            r.w = fmaxf(acc[i][j0 + 3] + bv[j0 + 3], 0.f);
            *(float4*)(out + (size_t)gm * 128 + tx * 8 + j0) = r;
        }
    }
}

// ---------------- graph boundaries (batch is sorted) -----------------------
__global__ void bounds_kernel(const int* __restrict__ batch) {
    int n = blockIdx.x * blockDim.x + threadIdx.x;
    if (n >= NN) return;
    int b  = batch[n];
    int bp = (n == 0) ? -1 : batch[n - 1];
    for (int g = bp + 1; g <= b; g++) g_gstart[g] = n;
    if (n == NN - 1)
        for (int g = b + 1; g <= NG; g++) g_gstart[g] = NN;
}

// ---------------- mean pool + classifier (block per graph) -----------------
__global__ void poolcls_kernel(const float* __restrict__ Wcls,
                               const float* __restrict__ bcls,
                               float* __restrict__ out) {
    __shared__ float mean[DD];
    int g = blockIdx.x;
    int d = threadIdx.x;
    int n0 = g_gstart[g], n1 = g_gstart[g + 1];
    float s = 0.f;
    for (int n = n0; n < n1; n++) s += g_h2[(size_t)n * DD + d];
    float c = (float)(n1 - n0);
    mean[d] = s / fmaxf(c, 1.f);
    __syncthreads();
    if (d < NC) {
        float a = bcls[d];
        for (int k = 0; k < DD; k++) a += mean[k] * Wcls[k * NC + d];
        out[g * NC + d] = a;
    }
}

// ---------------- launch ----------------------------------------------------
extern "C" void kernel_launch(void* const* d_in, const int* in_sizes, int n_in,
                              void* d_out, int out_size) {
    const float* x      = (const float*)d_in[0];
    const int*   ei     = (const int*)d_in[1];
    const int*   et     = (const int*)d_in[2];
    const int*   batch  = (const int*)d_in[3];
    const float* Wrel1  = (const float*)d_in[4];
    const float* Wroot1 = (const float*)d_in[5];
    const float* b1     = (const float*)d_in[6];
    const float* Wrel2  = (const float*)d_in[7];
    const float* Wroot2 = (const float*)d_in[8];
    const float* b2     = (const float*)d_in[9];
    const float* Wcls   = (const float*)d_in[10];
    const float* bcls   = (const float*)d_in[11];
    float*       out    = (float*)d_out;

    const int TB = 256;
    // edge CSR (once; reused by both layers)
    zero_cnt_kernel<<<(NRSEG + TB - 1) / TB, TB>>>();
    hist_kernel<<<(EE + TB - 1) / TB, TB>>>(ei, et);
    scan_kernel<<<1, 1024>>>();
    scatter_kernel<<<(EE + TB - 1) / TB, TB>>>();

    int agg_blocks  = NRSEG / 8;                 // warp per segment, 8 warps/block
    int gemm_blocks = (NN + TM - 1) / TM;        // 391

    // layer 1
    agg_kernel<0><<<agg_blocks, TB>>>((const float4*)x);
    gemm_kernel<0><<<gemm_blocks, TB>>>(x, Wrel1, Wroot1, b1, NN);
    // layer 2
    agg_kernel<1><<<agg_blocks, TB>>>(nullptr);
    gemm_kernel<1><<<gemm_blocks, TB>>>(nullptr, Wrel2, Wroot2, b2, NN);
    // pool + classify
    bounds_kernel<<<(NN + TB - 1) / TB, TB>>>(batch);
    poolcls_kernel<<<NG, DD>>>(Wcls, bcls, out);
}

// round 5
// speedup vs baseline: 1.3776x; 1.3776x over previous
#include <cuda_runtime.h>
#include <cuda_bf16.h>
#include <cstdint>

#define NN    50000
#define EE    800000
#define RR    4
#define NRSEG (NN*RR)
#define DD    128
#define NG    128
#define NC    16
#define KK    640                 // 512 (rel) + 128 (root)
#define NKC   10                  // K chunks of 64
#define MT    128
#define GEMM_BLOCKS ((NN + MT - 1) / MT)   // 391

// smem tile geometry: 128 rows x 64 bf16, padded to 72 bf16 (144 B) per row
#define ROWB        144
#define TILEB       (128 * ROWB)          // 18432
#define STAGEB      (4 * TILEB)           // Ahi, Alo, Bhi, Blo = 73728
#define SMEM_TOTAL  (2 * STAGEB)          // 147456

// ---------------- scratch (device globals) ----------------------------------
__device__ int   g_cnt[NRSEG];
__device__ int   g_off[NRSEG + 1];
__device__ int   g_cur[NRSEG];
__device__ int   g_srce[EE];
__device__ int   g_sege[EE];
__device__ int   g_srcs[EE];
__device__ __nv_bfloat16 g_shi[NRSEG * DD];   // segment means hi (== A[:, :512])
__device__ __nv_bfloat16 g_slo[NRSEG * DD];   // lo part
__device__ __nv_bfloat16 g_xbhi[NN * DD],  g_xblo[NN * DD];    // x residual bf16 pair
__device__ __nv_bfloat16 g_h1bhi[NN * DD], g_h1blo[NN * DD];   // h1 residual bf16 pair
__device__ __nv_bfloat16 g_B1hi[DD * KK], g_B1lo[DD * KK];     // weights [N=128, K=640]
__device__ __nv_bfloat16 g_B2hi[DD * KK], g_B2lo[DD * KK];
__device__ float g_h1[NN * DD];
__device__ float g_h2[NN * DD];
__device__ int   g_gstart[NG + 1];

// ---------------- helpers ----------------------------------------------------
__device__ __forceinline__ uint32_t smem_u32(const void* p) {
    uint32_t a;
    asm("{ .reg .u64 t; cvta.to.shared.u64 t, %1; cvt.u32.u64 %0, t; }"
        : "=r"(a) : "l"(p));
    return a;
}

__device__ __forceinline__ void cp16(uint32_t dst, const void* src) {
    asm volatile("cp.async.cg.shared.global [%0], [%1], 16;" :: "r"(dst), "l"(src));
}
#define CP_COMMIT() asm volatile("cp.async.commit_group;" ::: "memory")
#define CP_WAIT(n)  asm volatile("cp.async.wait_group %0;" :: "n"(n) : "memory")

__device__ __forceinline__ void mma_bf16(float* d, const uint32_t* a,
                                         uint32_t b0, uint32_t b1) {
    asm volatile(
        "mma.sync.aligned.m16n8k16.row.col.f32.bf16.bf16.f32 "
        "{%0,%1,%2,%3}, {%4,%5,%6,%7}, {%8,%9}, {%0,%1,%2,%3};\n"
        : "+f"(d[0]), "+f"(d[1]), "+f"(d[2]), "+f"(d[3])
        : "r"(a[0]), "r"(a[1]), "r"(a[2]), "r"(a[3]), "r"(b0), "r"(b1));
}

__device__ __forceinline__ void split_bf16(float v, __nv_bfloat16& hi, __nv_bfloat16& lo) {
    hi = __float2bfloat16_rn(v);
    lo = __float2bfloat16_rn(v - __bfloat162float(hi));
}

// ---------------- edge preprocessing ----------------------------------------
__global__ void zero_cnt_kernel() {
    int i = blockIdx.x * blockDim.x + threadIdx.x;
    if (i < NRSEG) g_cnt[i] = 0;
}

__global__ void hist_kernel(const int* __restrict__ ei,
                            const int* __restrict__ et) {
    int e = blockIdx.x * blockDim.x + threadIdx.x;
    if (e >= EE) return;
    int src = ei[e];
    int dst = ei[EE + e];
    int ty  = et[e];
    int seg = dst * RR + ty;
    g_srce[e] = src;
    g_sege[e] = seg;
    atomicAdd(&g_cnt[seg], 1);
}

__global__ void scan_kernel() {
    __shared__ int sh[1024];
    int t = threadIdx.x;
    const int C = (NRSEG + 1023) / 1024;
    int b = t * C;
    int e = min(b + C, NRSEG);
    int s = 0;
    for (int i = b; i < e; i++) s += g_cnt[i];
    sh[t] = s;
    __syncthreads();
    for (int d = 1; d < 1024; d <<= 1) {
        int v = (t >= d) ? sh[t - d] : 0;
        __syncthreads();
        sh[t] += v;
        __syncthreads();
    }
    int excl = sh[t] - s;
    if (t == 1023) g_off[NRSEG] = sh[1023];
    int a = excl;
    for (int i = b; i < e; i++) {
        g_off[i] = a;
        g_cur[i] = a;
        a += g_cnt[i];
    }
}

__global__ void scatter_kernel() {
    int e = blockIdx.x * blockDim.x + threadIdx.x;
    if (e >= EE) return;
    int seg = g_sege[e];
    int pos = atomicAdd(&g_cur[seg], 1);
    g_srcs[pos] = g_srce[e];
}

// ---------------- conversions -----------------------------------------------
// weights -> [N=128 rows (f), K=640 cols] bf16 hi/lo (transpose)
__global__ void convw_kernel(const float* __restrict__ Wrel1,
                             const float* __restrict__ Wroot1,
                             const float* __restrict__ Wrel2,
                             const float* __restrict__ Wroot2) {
    int i = blockIdx.x * blockDim.x + threadIdx.x;
    if (i >= 2 * DD * KK) return;
    int layer = i / (DD * KK);
    int rem   = i % (DD * KK);
    int f = rem / KK;
    int k = rem % KK;
    const float* Wr = layer ? Wrel2 : Wrel1;
    const float* Wo = layer ? Wroot2 : Wroot1;
    float v = (k < 512) ? Wr[k * DD + f] : Wo[(k - 512) * DD + f];
    __nv_bfloat16 hi, lo;
    split_bf16(v, hi, lo);
    if (layer) { g_B2hi[rem] = hi; g_B2lo[rem] = lo; }
    else       { g_B1hi[rem] = hi; g_B1lo[rem] = lo; }
}

__global__ void convx_kernel(const float* __restrict__ x) {
    int i = blockIdx.x * blockDim.x + threadIdx.x;
    if (i >= NN * DD) return;
    __nv_bfloat16 hi, lo;
    split_bf16(x[i], hi, lo);
    g_xbhi[i] = hi;
    g_xblo[i] = lo;
}

// ---------------- per-(dst,rel) segment mean -> bf16 hi/lo -------------------
template<int LAYER>
__global__ void agg_kernel(const float4* __restrict__ Xin) {
    const float4* X4 = (LAYER == 0) ? Xin : (const float4*)g_h1;
    int w    = (blockIdx.x * blockDim.x + threadIdx.x) >> 5;
    int lane = threadIdx.x & 31;
    if (w >= NRSEG) return;
    int o0 = g_off[w];
    int o1 = g_off[w + 1];
    float4 acc = make_float4(0.f, 0.f, 0.f, 0.f);
    for (int i = o0; i < o1; i++) {
        int s = g_srcs[i];
        float4 v = X4[s * 32 + lane];
        acc.x += v.x; acc.y += v.y; acc.z += v.z; acc.w += v.w;
    }
    float norm = (o1 > o0) ? 1.f / (float)(o1 - o0) : 0.f;
    float vals[4] = {acc.x * norm, acc.y * norm, acc.z * norm, acc.w * norm};
    union { __nv_bfloat16 h[4]; uint2 u; } hh, ll;
#pragma unroll
    for (int j = 0; j < 4; j++) split_bf16(vals[j], hh.h[j], ll.h[j]);
    size_t idx = (size_t)w * DD + lane * 4;
    *(uint2*)(g_shi + idx) = hh.u;
    *(uint2*)(g_slo + idx) = ll.u;
}

// ---------------- HMMA GEMM: out = relu(A[128,640] @ B^T + bias) -------------
// A rows = nodes (seg means cols 0..511, residual 512..639), B = [128,640].
// 3-product bf16 split: hh + hl + lh. cp.async 2-stage pipeline.
template<int LAYER>
__global__ void __launch_bounds__(256)
mma_gemm_kernel(const float* __restrict__ bias) {
    extern __shared__ char smem[];
    const uint32_t sb = smem_u32(smem);
    const int tid  = threadIdx.x;
    const int lane = tid & 31, wid = tid >> 5;
    const int wm = wid & 3, wn = wid >> 2;    // 4 m-warps x 2 n-warps
    const int m0 = blockIdx.x * MT;

    const __nv_bfloat16* Bh = (LAYER == 0) ? g_B1hi : g_B2hi;
    const __nv_bfloat16* Bl = (LAYER == 0) ? g_B1lo : g_B2lo;
    const __nv_bfloat16* Rh = (LAYER == 0) ? g_xbhi : g_h1bhi;
    const __nv_bfloat16* Rl = (LAYER == 0) ? g_xblo : g_h1blo;
    float* Hout = (LAYER == 0) ? g_h1 : g_h2;

    // prefetch one k-chunk into stage (kc&1)
    auto prefetch = [&](int kc) {
        uint32_t st = sb + (uint32_t)(kc & 1) * STAGEB;
        int q = tid & 7;                       // 16B chunk within row
#pragma unroll
        for (int i = 0; i < 4; i++) {
            int row = i * 32 + (tid >> 3);
            uint32_t d = st + row * ROWB + q * 16;
            int node = min(m0 + row, NN - 1);
            const __nv_bfloat16 *ah, *al;
            size_t ao;
            if (kc < 8) { ah = g_shi; al = g_slo; ao = (size_t)node * 512 + kc * 64 + q * 8; }
            else        { ah = Rh;    al = Rl;    ao = (size_t)node * 128 + (kc - 8) * 64 + q * 8; }
            cp16(d,             ah + ao);
            cp16(d + TILEB,     al + ao);
            size_t bo = (size_t)row * KK + kc * 64 + q * 8;
            cp16(d + 2 * TILEB, Bh + bo);
            cp16(d + 3 * TILEB, Bl + bo);
        }
    };

    float acc[2][8][4];
#pragma unroll
    for (int f = 0; f < 2; f++)
#pragma unroll
        for (int j = 0; j < 8; j++)
#pragma unroll
            for (int q = 0; q < 4; q++) acc[f][j][q] = 0.f;

    prefetch(0);
    CP_COMMIT();

    for (int kc = 0; kc < NKC; kc++) {
        if (kc + 1 < NKC) {
            prefetch(kc + 1);
            CP_COMMIT();
            CP_WAIT(1);
        } else {
            CP_WAIT(0);
        }
        __syncthreads();
        const char* st = smem + (kc & 1) * STAGEB;
#pragma unroll
        for (int ks = 0; ks < 4; ks++) {
            int kb2 = (ks * 16 + (lane & 3) * 2) * 2;      // byte offset of k within row
            uint32_t ahi[2][4], alo[2][4];
#pragma unroll
            for (int f = 0; f < 2; f++) {
                int r = wm * 32 + f * 16 + (lane >> 2);
                const char* pa = st + r * ROWB + kb2;
                ahi[f][0] = *(const uint32_t*)(pa);
                ahi[f][1] = *(const uint32_t*)(pa + 8 * ROWB);
                ahi[f][2] = *(const uint32_t*)(pa + 16);
                ahi[f][3] = *(const uint32_t*)(pa + 8 * ROWB + 16);
                const char* pl = pa + TILEB;
                alo[f][0] = *(const uint32_t*)(pl);
                alo[f][1] = *(const uint32_t*)(pl + 8 * ROWB);
                alo[f][2] = *(const uint32_t*)(pl + 16);
                alo[f][3] = *(const uint32_t*)(pl + 8 * ROWB + 16);
            }
#pragma unroll
            for (int j = 0; j < 8; j++) {
                int n = wn * 64 + j * 8 + (lane >> 2);
                const char* pb = st + 2 * TILEB + n * ROWB + kb2;
                uint32_t bh0 = *(const uint32_t*)(pb);
                uint32_t bh1 = *(const uint32_t*)(pb + 16);
                uint32_t bl0 = *(const uint32_t*)(pb + TILEB);
                uint32_t bl1 = *(const uint32_t*)(pb + TILEB + 16);
#pragma unroll
                for (int f = 0; f < 2; f++) {
                    mma_bf16(acc[f][j], ahi[f], bh0, bh1);
                    mma_bf16(acc[f][j], ahi[f], bl0, bl1);
                    mma_bf16(acc[f][j], alo[f], bh0, bh1);
                }
            }
        }
        __syncthreads();
    }

    // epilogue: bias + relu -> fp32 h (+ bf16 split pair for next layer)
#pragma unroll
    for (int f = 0; f < 2; f++) {
#pragma unroll
        for (int j = 0; j < 8; j++) {
            int c  = wn * 64 + j * 8 + (lane & 3) * 2;
            float b0 = bias[c], b1 = bias[c + 1];
#pragma unroll
            for (int h = 0; h < 2; h++) {
                int gm = m0 + wm * 32 + f * 16 + (lane >> 2) + h * 8;
                if (gm >= NN) continue;
                float v0 = fmaxf(acc[f][j][h * 2 + 0] + b0, 0.f);
                float v1 = fmaxf(acc[f][j][h * 2 + 1] + b1, 0.f);
                *(float2*)(Hout + (size_t)gm * DD + c) = make_float2(v0, v1);
                if (LAYER == 0) {
                    __nv_bfloat16 h0, l0, h1c, l1;
                    split_bf16(v0, h0, l0);
                    split_bf16(v1, h1c, l1);
                    union { __nv_bfloat16 h[2]; uint32_t u; } uh, ul;
                    uh.h[0] = h0; uh.h[1] = h1c;
                    ul.h[0] = l0; ul.h[1] = l1;
                    *(uint32_t*)(g_h1bhi + (size_t)gm * DD + c) = uh.u;
                    *(uint32_t*)(g_h1blo + (size_t)gm * DD + c) = ul.u;
                }
            }
        }
    }
}

// ---------------- graph boundaries ------------------------------------------
__global__ void bounds_kernel(const int* __restrict__ batch) {
    int n = blockIdx.x * blockDim.x + threadIdx.x;
    if (n >= NN) return;
    int b  = batch[n];
    int bp = (n == 0) ? -1 : batch[n - 1];
    for (int g = bp + 1; g <= b; g++) g_gstart[g] = n;
    if (n == NN - 1)
        for (int g = b + 1; g <= NG; g++) g_gstart[g] = NN;
}

// ---------------- mean pool + classifier ------------------------------------
__global__ void poolcls_kernel(const float* __restrict__ Wcls,
                               const float* __restrict__ bcls,
                               float* __restrict__ out) {
    __shared__ float mean[DD];
    int g = blockIdx.x;
    int d = threadIdx.x;
    int n0 = g_gstart[g], n1 = g_gstart[g + 1];
    float s = 0.f;
    for (int n = n0; n < n1; n++) s += g_h2[(size_t)n * DD + d];
    float c = (float)(n1 - n0);
    mean[d] = s / fmaxf(c, 1.f);
    __syncthreads();
    if (d < NC) {
        float a = bcls[d];
        for (int k = 0; k < DD; k++) a += mean[k] * Wcls[k * NC + d];
        out[g * NC + d] = a;
    }
}

// ---------------- launch -----------------------------------------------------
extern "C" void kernel_launch(void* const* d_in, const int* in_sizes, int n_in,
                              void* d_out, int out_size) {
    const float* x      = (const float*)d_in[0];
    const int*   ei     = (const int*)d_in[1];
    const int*   et     = (const int*)d_in[2];
    const int*   batch  = (const int*)d_in[3];
    const float* Wrel1  = (const float*)d_in[4];
    const float* Wroot1 = (const float*)d_in[5];
    const float* b1     = (const float*)d_in[6];
    const float* Wrel2  = (const float*)d_in[7];
    const float* Wroot2 = (const float*)d_in[8];
    const float* b2     = (const float*)d_in[9];
    const float* Wcls   = (const float*)d_in[10];
    const float* bcls   = (const float*)d_in[11];
    float*       out    = (float*)d_out;

    cudaFuncSetAttribute(mma_gemm_kernel<0>,
                         cudaFuncAttributeMaxDynamicSharedMemorySize, SMEM_TOTAL);
    cudaFuncSetAttribute(mma_gemm_kernel<1>,
                         cudaFuncAttributeMaxDynamicSharedMemorySize, SMEM_TOTAL);

    const int TB = 256;
    // edge CSR (once; reused by both layers)
    zero_cnt_kernel<<<(NRSEG + TB - 1) / TB, TB>>>();
    hist_kernel<<<(EE + TB - 1) / TB, TB>>>(ei, et);
    scan_kernel<<<1, 1024>>>();
    scatter_kernel<<<(EE + TB - 1) / TB, TB>>>();

    // weight / input bf16 splits
    convw_kernel<<<(2 * DD * KK + TB - 1) / TB, TB>>>(Wrel1, Wroot1, Wrel2, Wroot2);
    convx_kernel<<<(NN * DD + TB - 1) / TB, TB>>>(x);

    int agg_blocks = NRSEG / 8;

    // layer 1
    agg_kernel<0><<<agg_blocks, TB>>>((const float4*)x);
    mma_gemm_kernel<0><<<GEMM_BLOCKS, 256, SMEM_TOTAL>>>(b1);
    // layer 2
    agg_kernel<1><<<agg_blocks, TB>>>(nullptr);
    mma_gemm_kernel<1><<<GEMM_BLOCKS, 256, SMEM_TOTAL>>>(b2);
    // pool + classify
    bounds_kernel<<<(NN + TB - 1) / TB, TB>>>(batch);
    poolcls_kernel<<<NG, DD>>>(Wcls, bcls, out);
}